// round 1
// baseline (speedup 1.0000x reference)
#include <cuda_runtime.h>
#include <stdint.h>

// Problem dims (fixed by the dataset)
#define Mv 128          // number of variant sequences
#define Nv 256          // sequence length
#define Cv 22           // classes
#define TILE (Cv*Cv)    // 484 floats per (i,j) coupling tile
#define JC 8            // j-tiles per pipeline chunk
#define NCHUNK (Nv/JC)  // 32 chunks
#define NSTAGES 3
#define STAGE_FLOATS (JC*TILE)   // 3872 floats = 15488 B
#define CHALF 11        // c-values per thread (2 threads per m)

// transposed variant classes: g_dsel[j*Mv + m] = variant[m, j]  (0..21 fits in a byte)
__device__ __align__(16) unsigned char g_dsel[Nv*Mv];

// ---------------------------------------------------------------------------
// prep: transpose variant -> byte array for coalesced per-j access
// ---------------------------------------------------------------------------
__global__ void prep_kernel(const int* __restrict__ variant) {
    int idx = blockIdx.x * blockDim.x + threadIdx.x;   // idx over [m, j], coalesced read
    if (idx < Mv * Nv) {
        int m = idx / Nv;
        int j = idx - m * Nv;
        g_dsel[j * Mv + m] = (unsigned char)variant[idx];
    }
}

// ---------------------------------------------------------------------------
// main: one CTA per position i.  hi[m,c] = sum_j s(d_mj) * eij[i,j,c,d_mj]
// ---------------------------------------------------------------------------
__device__ __forceinline__ void issue_chunk(const float* gbase, int k, int t,
                                            float (*sE)[STAGE_FLOATS]) {
    if (k < NCHUNK) {
        const char* src = (const char*)(gbase + (size_t)k * STAGE_FLOATS);
        uint32_t dst = (uint32_t)__cvta_generic_to_shared(&sE[k % NSTAGES][0]);
        #pragma unroll 1
        for (int u = t; u < STAGE_FLOATS / 4; u += 256) {
            asm volatile("cp.async.cg.shared.global [%0], [%1], 16;\n"
                         :: "r"(dst + u * 16), "l"(src + (size_t)u * 16));
        }
    }
    asm volatile("cp.async.commit_group;\n");
}

__global__ __launch_bounds__(256) void potts_kernel(
    const float* __restrict__ eij,
    const float* __restrict__ ei,
    const float* __restrict__ mask_vec,
    float* __restrict__ motifs,     // [Mv, Nv, Cv]
    float* __restrict__ logits)     // [Mv, Nv]
{
    __shared__ __align__(16) float sE[NSTAGES][STAGE_FLOATS];
    __shared__ float smask[32];
    __shared__ float sei[Cv];

    const int i   = blockIdx.x;
    const int t   = threadIdx.x;
    const int m   = t & (Mv - 1);
    const int half= t >> 7;
    const int c0  = half * CHALF;

    if (t < Cv) {
        smask[t] = mask_vec[t];
        sei[t]   = ei[i * Cv + t];
    }

    const float* gbase = eij + (size_t)i * (Nv * TILE);

    float acc[CHALF];
    #pragma unroll
    for (int cc = 0; cc < CHALF; ++cc) acc[cc] = 0.0f;

    // prime the pipeline
    for (int k = 0; k < NSTAGES - 1; ++k) issue_chunk(gbase, k, t, sE);

    for (int k = 0; k < NCHUNK; ++k) {
        asm volatile("cp.async.wait_group %0;\n" :: "n"(NSTAGES - 2));
        __syncthreads();

        const float* buf = sE[k % NSTAGES];
        const int jbase = k * JC;
        #pragma unroll
        for (int jj = 0; jj < JC; ++jj) {
            const int j = jbase + jj;
            const int d = g_dsel[j * Mv + m];
            const float s = smask[d];          // LDS: distinct d -> distinct banks
            const float* row = buf + jj * TILE + c0 * Cv + d;
            #pragma unroll
            for (int cc = 0; cc < CHALF; ++cc)
                acc[cc] = fmaf(s, row[cc * Cv], acc[cc]);   // conflict-free LDS
        }

        __syncthreads();
        issue_chunk(gbase, k + NSTAGES - 1, t, sE);
    }

    // epilogue: motifs = ei + hi ; logits = motifs[..., v[m,i]]
    const int vmi = g_dsel[i * Mv + m];
    float* mout = motifs + ((size_t)m * Nv + i) * Cv;
    #pragma unroll
    for (int cc = 0; cc < CHALF; ++cc) {
        const int c = c0 + cc;
        const float v = acc[cc] + sei[c];
        mout[c] = v;
        if (c == vmi) logits[m * Nv + i] = v;
    }
}

// ---------------------------------------------------------------------------
// finalize: variant_logit[m] = sigma * sum_i (logits[m,i]-logits[0,i]) * vm[m,i]*vm[0,i]
// ---------------------------------------------------------------------------
__global__ void finalize_kernel(const float* __restrict__ logits,
                                const float* __restrict__ vmask,
                                const float* __restrict__ sigma,
                                float* __restrict__ out) {
    const int m = blockIdx.x;
    const int t = threadIdx.x;      // 256 == Nv
    __shared__ float red[Nv];
    const float lm = logits[m * Nv + t];
    const float l0 = logits[t];
    const float w  = vmask[m * Nv + t] * vmask[t];
    red[t] = (lm - l0) * w;
    __syncthreads();
    for (int s = Nv / 2; s > 0; s >>= 1) {
        if (t < s) red[t] += red[t + s];
        __syncthreads();
    }
    if (t == 0) out[m] = sigma[0] * red[0];
}

// ---------------------------------------------------------------------------
extern "C" void kernel_launch(void* const* d_in, const int* in_sizes, int n_in,
                              void* d_out, int out_size) {
    // Resolve inputs by element count (robust to ordering), falling back to
    // declaration order for the two same-sized tensors (variant, variant_mask).
    int idx_eij = 2, idx_ei = 3, idx_mask = 4, idx_sigma = 5;
    int big1 = 0, big2 = 1;
    {
        int b1 = -1, b2 = -1;
        for (int q = 0; q < n_in; ++q) {
            int s = in_sizes[q];
            if (s == Nv * Nv * Cv * Cv)      idx_eij = q;
            else if (s == Nv * Cv)           idx_ei = q;
            else if (s == Cv)                idx_mask = q;
            else if (s == 1)                 idx_sigma = q;
            else if (s == Mv * Nv) { if (b1 < 0) b1 = q; else b2 = q; }
        }
        if (b1 >= 0) big1 = b1;
        if (b2 >= 0) big2 = b2;
    }

    const int*   variant = (const int*)d_in[big1];
    const float* vmask   = (const float*)d_in[big2];
    const float* eij     = (const float*)d_in[idx_eij];
    const float* ei      = (const float*)d_in[idx_ei];
    const float* maskv   = (const float*)d_in[idx_mask];
    const float* sigma   = (const float*)d_in[idx_sigma];

    float* out    = (float*)d_out;
    float* motifs = out;                               // [128,256,22]
    float* logits = out + (size_t)Mv * Nv * Cv;        // [128,256]
    float* vlog   = logits + (size_t)Mv * Nv;          // [128,1]

    prep_kernel<<<(Mv * Nv + 255) / 256, 256>>>(variant);
    potts_kernel<<<Nv, 256>>>(eij, ei, maskv, motifs, logits);
    finalize_kernel<<<Mv, Nv>>>(logits, vmask, sigma, vlog);
}